// round 1
// baseline (speedup 1.0000x reference)
#include <cuda_runtime.h>
#include <math.h>
#include <stdint.h>

#define G 64      // B*T graphs
#define NN 1024   // nodes per graph
#define FF 64     // features
#define JT 128    // j tile width staged in smem
#define WARPS 16  // warps per block in attn kernel

// Scratch (device globals: allocation-free rule)
__device__ float g_Wh[G * NN * FF];   // 16 MB
__device__ float g_s1[G * NN];
__device__ float g_s2[G * NN];

// ---------------------------------------------------------------------------
// Kernel A: Wh = h @ W, s1 = Wh@a1, s2 = Wh@a2.  One warp per node.
// ---------------------------------------------------------------------------
__global__ __launch_bounds__(256) void wh_kernel(const float* __restrict__ h,
                                                 const float* __restrict__ W,
                                                 const float* __restrict__ a) {
    __shared__ float2 Ws[64 * 32];   // 16 KB, same linear layout as W
    int tid = threadIdx.x;
    {
        const float4* W4 = (const float4*)W;
        float4* Ws4 = (float4*)Ws;
        #pragma unroll
        for (int i = 0; i < 4; i++) Ws4[tid + i * 256] = W4[tid + i * 256];
    }
    __syncthreads();

    int lane = tid & 31;
    int warp = tid >> 5;
    int node = blockIdx.x * 8 + warp;            // 0 .. G*NN-1

    float2 hv = ((const float2*)(h + (size_t)node * FF))[lane];

    float accx = 0.f, accy = 0.f;
    #pragma unroll
    for (int k = 0; k < 64; k++) {
        float hk = __shfl_sync(0xffffffffu, (k & 1) ? hv.y : hv.x, k >> 1);
        float2 w2 = Ws[k * 32 + lane];
        accx = fmaf(hk, w2.x, accx);
        accy = fmaf(hk, w2.y, accy);
    }
    ((float2*)(g_Wh + (size_t)node * FF))[lane] = make_float2(accx, accy);

    // scores
    float2 a1 = __ldg(((const float2*)a) + lane);        // a[2l], a[2l+1]
    float2 a2 = __ldg(((const float2*)a) + 32 + lane);   // a[64+2l], ...
    float s1 = accx * a1.x + accy * a1.y;
    float s2 = accx * a2.x + accy * a2.y;
    #pragma unroll
    for (int off = 16; off; off >>= 1) {
        s1 += __shfl_xor_sync(0xffffffffu, s1, off);
        s2 += __shfl_xor_sync(0xffffffffu, s2, off);
    }
    if (lane == 0) { g_s1[node] = s1; g_s2[node] = s2; }
}

// ---------------------------------------------------------------------------
// Kernel C: masked-softmax attention + att@Wh + ELU.
// Block = 512 threads = 16 warps; each warp owns 4 rows i; 64 rows per block.
// Single pass over j (no max subtraction needed: |s1+s2| small, exp safe).
// ---------------------------------------------------------------------------
extern __shared__ float smem_c[];

__global__ __launch_bounds__(512) void attn_kernel(const int* __restrict__ adj,
                                                   float* __restrict__ out) {
    float*  Whs = smem_c;                       // JT*64 floats      (32 KB)
    float*  s2s = smem_c + JT * 64;             // JT floats         (512 B)
    float2* ps  = (float2*)(smem_c + JT * 64 + JT);  // [warp][2][JT] (32 KB)

    int tid  = threadIdx.x;
    int lane = tid & 31;
    int w    = tid >> 5;
    int g    = blockIdx.x >> 4;
    int i0   = (blockIdx.x & 15) * 64 + w * 4;

    float s1r[4];
    #pragma unroll
    for (int r = 0; r < 4; r++) s1r[r] = g_s1[g * NN + i0 + r];

    // acc[0]={r0f0,r1f0} acc[1]={r0f1,r1f1} acc[2]={r2f0,r3f0} acc[3]={r2f1,r3f1}
    unsigned long long acc[4] = {0ull, 0ull, 0ull, 0ull};
    float Zl[4] = {0.f, 0.f, 0.f, 0.f};

    const int*   adjg = adj + ((size_t)g * NN + i0) * NN;
    const float* Whg  = g_Wh + (size_t)g * NN * FF;
    float2* psA = &ps[(w * 2 + 0) * JT];
    float2* psB = &ps[(w * 2 + 1) * JT];

    for (int jt = 0; jt < NN / JT; jt++) {
        int j0 = jt * JT;
        __syncthreads();   // previous tile's Whs reads complete
        {
            const float4* src = (const float4*)(Whg + j0 * FF);
            float4* dst = (float4*)Whs;
            #pragma unroll
            for (int q = 0; q < 4; q++) dst[tid + q * 512] = src[tid + q * 512];
            if (tid < JT) s2s[tid] = g_s2[g * NN + j0 + tid];
        }
        __syncthreads();

        // phase 1: p values for 4 rows x 128 j
        #pragma unroll
        for (int c = 0; c < 4; c++) {
            int jj = c * 32 + lane;
            float s2v = s2s[jj];
            float pv[4];
            #pragma unroll
            for (int r = 0; r < 4; r++) {
                int av = adjg[(size_t)r * NN + j0 + jj];
                float x = s1r[r] + s2v;
                float e = fmaxf(x, 0.2f * x);         // leaky_relu
                float p = av ? __expf(e) : 0.0f;      // masked -> weight 0
                Zl[r] += p;
                pv[r] = p;
            }
            psA[jj] = make_float2(pv[0], pv[1]);
            psB[jj] = make_float2(pv[2], pv[3]);
        }
        __syncwarp();

        // phase 2: rank-JT update with packed f32x2 FMA (rows packed)
        #pragma unroll 8
        for (int jj = 0; jj < JT; jj++) {
            unsigned long long p01 = *(const unsigned long long*)&psA[jj]; // bcast
            unsigned long long p23 = *(const unsigned long long*)&psB[jj]; // bcast
            float w0 = Whs[jj * 64 + 2 * lane];
            float w1 = Whs[jj * 64 + 2 * lane + 1];
            unsigned long long wd0, wd1;
            asm("mov.b64 %0, {%1, %1};" : "=l"(wd0) : "r"(__float_as_uint(w0)));
            asm("mov.b64 %0, {%1, %1};" : "=l"(wd1) : "r"(__float_as_uint(w1)));
            asm("fma.rn.f32x2 %0, %1, %2, %0;" : "+l"(acc[0]) : "l"(p01), "l"(wd0));
            asm("fma.rn.f32x2 %0, %1, %2, %0;" : "+l"(acc[1]) : "l"(p01), "l"(wd1));
            asm("fma.rn.f32x2 %0, %1, %2, %0;" : "+l"(acc[2]) : "l"(p23), "l"(wd0));
            asm("fma.rn.f32x2 %0, %1, %2, %0;" : "+l"(acc[3]) : "l"(p23), "l"(wd1));
        }
    }

    // reduce Z across lanes (each lane held a disjoint subset of j)
    #pragma unroll
    for (int r = 0; r < 4; r++) {
        #pragma unroll
        for (int off = 16; off; off >>= 1)
            Zl[r] += __shfl_xor_sync(0xffffffffu, Zl[r], off);
    }

    // unpack, normalize, ELU, write
    float af[4][2];
    {
        uint2 u;
        u = *(uint2*)&acc[0]; af[0][0] = __uint_as_float(u.x); af[1][0] = __uint_as_float(u.y);
        u = *(uint2*)&acc[1]; af[0][1] = __uint_as_float(u.x); af[1][1] = __uint_as_float(u.y);
        u = *(uint2*)&acc[2]; af[2][0] = __uint_as_float(u.x); af[3][0] = __uint_as_float(u.y);
        u = *(uint2*)&acc[3]; af[2][1] = __uint_as_float(u.x); af[3][1] = __uint_as_float(u.y);
    }
    #pragma unroll
    for (int r = 0; r < 4; r++) {
        float inv = 1.0f / Zl[r];
        float o0 = af[r][0] * inv;
        float o1 = af[r][1] * inv;
        o0 = o0 > 0.f ? o0 : expm1f(o0);   // ELU (alpha=1)
        o1 = o1 > 0.f ? o1 : expm1f(o1);
        ((float2*)(out + ((size_t)g * NN + i0 + r) * FF))[lane] = make_float2(o0, o1);
    }
}

// ---------------------------------------------------------------------------
extern "C" void kernel_launch(void* const* d_in, const int* in_sizes, int n_in,
                              void* d_out, int out_size) {
    const float* h   = (const float*)d_in[0];
    const int*   adj = (const int*)d_in[1];
    const float* W   = (const float*)d_in[2];
    const float* a   = (const float*)d_in[3];
    float* out = (float*)d_out;

    const int smem_bytes = (JT * 64 + JT) * 4 + WARPS * 2 * JT * 8; // 66048
    cudaFuncSetAttribute(attn_kernel, cudaFuncAttributeMaxDynamicSharedMemorySize,
                         smem_bytes);

    wh_kernel<<<G * NN / 8, 256>>>(h, W, a);
    attn_kernel<<<G * (NN / 64), 512, smem_bytes>>>(adj, out);
}